// round 3
// baseline (speedup 1.0000x reference)
#include <cuda_runtime.h>
#include <cstdint>

// PointPillarScatter on GB300 (sm_103a).
// out[b, c, y, x] = feat[p, c] where idxmap[b, y, x] == p, else 0.
//
// Architecture: invert the scatter into a coalesced gather.
//   K0: detect coords dtype (int32 vs int64) on-device      [~0 us]
//   K1: fill idxmap (6.9 MB) with -1                        [~2 us]
//   K2: scatter pillar INDEX (4B/cell), bounds-guarded      [~2 us]
//   K3: gather — coalesced float4 stores over the 438.8 MB output,
//       predicated feature loads for the ~7.5% occupied cells.
//
// Round-2 trap root cause: coords are int32 on device (JAX x64 disabled
// downgrades the reference's int64), so int64 reads produced wild scatter
// addresses -> cudaErrorInvalidAddressSpace. Fixed via on-device dtype
// detection + guarded writes.

#define NX_ 432
#define NY_ 496
#define C_  64
#define B_  8
#define NCELLS (B_ * NY_ * NX_)              // 1,714,176 cells
#define OUT_QUADS (B_ * C_ * NY_ * NX_ / 4)  // 27,426,816 float4 stores

__device__ int g_idxmap[NCELLS];
__device__ int g_is64;   // 1 if coords buffer is int64, 0 if int32

// ---------------------------------------------------------------------------
// Kernel 0: classify coords dtype. Single thread, deterministic.
// Under int64 interpretation, genuine int64 coords are all small non-negative
// ints. If the buffer is really int32, the (z,y)/(x,...) field reads pack two
// int32s -> huge values unless the high word is 0; over 64 random rows the
// probability of a false positive is ~0.
// ---------------------------------------------------------------------------
__global__ void detect_dtype_kernel(const void* __restrict__ coords, int P) {
    const long long* c64 = (const long long*)coords;
    int rows = P < 64 ? P : 64;           // 64 rows * 32B = 2KB, within either layout
    int ok = 1;
    for (int p = 0; p < rows; p++) {
        for (int j = 0; j < 4; j++) {
            long long v = c64[4 * p + j];
            if (v < 0 || v >= (1LL << 20)) ok = 0;
        }
    }
    g_is64 = ok;
}

// ---------------------------------------------------------------------------
// Kernel 1: fill idxmap with -1.
// ---------------------------------------------------------------------------
__global__ void fill_idxmap_kernel() {
    int i = blockIdx.x * blockDim.x + threadIdx.x;
    if (i < NCELLS) g_idxmap[i] = -1;
}

// ---------------------------------------------------------------------------
// Kernel 2: scatter pillar index into idxmap, dtype-dispatched + guarded.
// coords row layout: (batch, z, y, x).
// ---------------------------------------------------------------------------
__global__ void scatter_idx_kernel(const void* __restrict__ coords, int P) {
    int p = blockIdx.x * blockDim.x + threadIdx.x;
    if (p >= P) return;
    int b, z, y, x;
    if (g_is64) {
        const long long* c = (const long long*)coords;
        b = (int)c[4 * p + 0];
        z = (int)c[4 * p + 1];
        y = (int)c[4 * p + 2];
        x = (int)c[4 * p + 3];
    } else {
        const int* c = (const int*)coords;
        b = c[4 * p + 0];
        z = c[4 * p + 1];
        y = c[4 * p + 2];
        x = c[4 * p + 3];
    }
    // Guarded: even if parsing is wrong, never produce a wild address.
    if (b < 0 || b >= B_) return;
    int lin = z + y * NX_ + x;            // matches reference (nz==1 -> z==0)
    if (lin < 0 || lin >= NY_ * NX_) return;
    g_idxmap[b * (NY_ * NX_) + lin] = p;
}

// ---------------------------------------------------------------------------
// Kernel 3: gather. One float4 per thread over [b, c, y, x4].
// idxmap reads are contiguous per warp and reused across 64 channels (L2).
// Feature matrix (32.8 MB) becomes L2-resident; output stores fully coalesced.
// ---------------------------------------------------------------------------
__global__ void gather_kernel(const float* __restrict__ feat,
                              float4* __restrict__ out) {
    int idx = blockIdx.x * blockDim.x + threadIdx.x;  // float4 index
    if (idx >= OUT_QUADS) return;

    const int XQ = NX_ / 4;          // 108
    int x4 = idx % XQ;
    int t  = idx / XQ;
    int y  = t % NY_;
    int t2 = t / NY_;
    int c  = t2 % C_;
    int b  = t2 / C_;

    int cell = b * (NY_ * NX_) + y * NX_ + x4 * 4;
    int m0 = g_idxmap[cell + 0];
    int m1 = g_idxmap[cell + 1];
    int m2 = g_idxmap[cell + 2];
    int m3 = g_idxmap[cell + 3];

    float4 v;
    v.x = (m0 < 0) ? 0.0f : feat[(size_t)m0 * C_ + c];
    v.y = (m1 < 0) ? 0.0f : feat[(size_t)m1 * C_ + c];
    v.z = (m2 < 0) ? 0.0f : feat[(size_t)m2 * C_ + c];
    v.w = (m3 < 0) ? 0.0f : feat[(size_t)m3 * C_ + c];

    out[idx] = v;
}

// ---------------------------------------------------------------------------
extern "C" void kernel_launch(void* const* d_in, const int* in_sizes, int n_in,
                              void* d_out, int out_size) {
    const float* feat   = (const float*)d_in[0];
    const void*  coords = d_in[1];
    int P = in_sizes[0] / C_;   // dtype-independent: features are [P, 64] f32

    constexpr int TPB = 256;
    detect_dtype_kernel<<<1, 1>>>(coords, P);
    fill_idxmap_kernel<<<(NCELLS + TPB - 1) / TPB, TPB>>>();
    scatter_idx_kernel<<<(P + TPB - 1) / TPB, TPB>>>(coords, P);
    gather_kernel<<<(OUT_QUADS + TPB - 1) / TPB, TPB>>>(feat, (float4*)d_out);
}

// round 4
// speedup vs baseline: 1.2844x; 1.2844x over previous
#include <cuda_runtime.h>
#include <cstdint>

// PointPillarScatter on GB300 (sm_103a).
// out[b, c, y, x] = feat[p, c] where idxmap[b, y, x] == p, else 0.
//
// Round 3 -> 4: gather was L1tex-bound (86.8%) not DRAM-bound (46.7%).
// New gather: tile-transpose through smem. One block = (b, y, 108 x-cells)
// across all 64 channels.
//   - idxmap read ONCE per cell (was 64x)
//   - occupied pillars' feature rows read contiguously as 16xfloat4 (was 64
//     scattered 4B loads each)
//   - pure coalesced float4 output stores, zeros selected from smem validity.

#define NX_ 432
#define NY_ 496
#define C_  64
#define B_  8
#define NCELLS (B_ * NY_ * NX_)      // 1,714,176
#define TILE   108                   // x-cells per block (432/4)
#define TILES_X (NX_ / TILE)         // 4
#define PITCH  112                   // TILE padded to /4 for LDS.128 + bank spread

__device__ __align__(16) int g_idxmap[NCELLS];
__device__ int g_is64;   // 1 if coords buffer is int64, 0 if int32

// ---------------------------------------------------------------------------
// Kernel 0: classify coords dtype (one warp). Genuine int64 coords are all
// small non-negative ints under int64 interpretation; int32 data read as
// int64 packs two fields -> huge values. 64 rows checked => robust.
// ---------------------------------------------------------------------------
__global__ void detect_dtype_kernel(const void* __restrict__ coords, int P) {
    const long long* c64 = (const long long*)coords;
    int rows = P < 64 ? P : 64;
    int lane = threadIdx.x;          // 32 threads
    int ok = 1;
    for (int p = lane; p < rows; p += 32) {
        for (int j = 0; j < 4; j++) {
            long long v = c64[4 * p + j];
            if (v < 0 || v >= (1LL << 20)) ok = 0;
        }
    }
    ok = __all_sync(0xFFFFFFFFu, ok);
    if (lane == 0) g_is64 = ok;
}

// ---------------------------------------------------------------------------
// Kernel 1: fill idxmap with -1, vectorized int4 (array is 16B-aligned).
// ---------------------------------------------------------------------------
__global__ void fill_idxmap_kernel() {
    int i = blockIdx.x * blockDim.x + threadIdx.x;
    if (i < NCELLS / 4) {
        reinterpret_cast<int4*>(g_idxmap)[i] = make_int4(-1, -1, -1, -1);
    }
}

// ---------------------------------------------------------------------------
// Kernel 2: scatter pillar index, dtype-dispatched + bounds-guarded.
// coords row layout: (batch, z, y, x).
// ---------------------------------------------------------------------------
__global__ void scatter_idx_kernel(const void* __restrict__ coords, int P) {
    int p = blockIdx.x * blockDim.x + threadIdx.x;
    if (p >= P) return;
    int b, z, y, x;
    if (g_is64) {
        const long long* c = (const long long*)coords;
        b = (int)c[4 * p + 0]; z = (int)c[4 * p + 1];
        y = (int)c[4 * p + 2]; x = (int)c[4 * p + 3];
    } else {
        const int* c = (const int*)coords;
        b = c[4 * p + 0]; z = c[4 * p + 1];
        y = c[4 * p + 2]; x = c[4 * p + 3];
    }
    if (b < 0 || b >= B_) return;
    int lin = z + y * NX_ + x;
    if (lin < 0 || lin >= NY_ * NX_) return;
    g_idxmap[b * (NY_ * NX_) + lin] = p;
}

// ---------------------------------------------------------------------------
// Kernel 3: tiled gather/transpose.
// Block = one (b, y, x-tile of 108 cells), 256 threads.
// ---------------------------------------------------------------------------
__global__ __launch_bounds__(256) void gather_kernel(const float* __restrict__ feat,
                                                     float* __restrict__ out) {
    __shared__ float s_tile[C_][PITCH];
    __shared__ __align__(16) int s_idx[PITCH];   // pillar index per cell (-1 empty)
    __shared__ int s_list[TILE];                 // compacted occupied cell ids
    __shared__ int s_n;

    int bx   = blockIdx.x;
    int tx   = bx % TILES_X;
    int y    = (bx / TILES_X) % NY_;
    int b    = bx / (TILES_X * NY_);
    int x0   = tx * TILE;
    int tid  = threadIdx.x;

    if (tid == 0) s_n = 0;
    if (tid >= TILE && tid < PITCH) s_idx[tid] = -1;   // pad cells invalid
    __syncthreads();

    // Phase 1: load idxmap once per cell; compact occupied cells.
    int cellbase = b * (NY_ * NX_) + y * NX_ + x0;
    if (tid < TILE) {
        int m = g_idxmap[cellbase + tid];
        s_idx[tid] = m;
        if (m >= 0) {
            int pos = atomicAdd(&s_n, 1);
            s_list[pos] = tid;
        }
    }
    __syncthreads();

    // Phase 2: contiguous, vectorized feature reads for occupied cells only.
    // Work item j = (occupied-cell slot, float4 chunk v of the 256B row).
    int n_occ = s_n;
    const float4* feat4 = (const float4*)feat;
    for (int j = tid; j < n_occ * 16; j += 256) {
        int slot = j >> 4;
        int v    = j & 15;
        int cell = s_list[slot];
        int p    = s_idx[cell];
        float4 f = feat4[(size_t)p * 16 + v];
        s_tile[4 * v + 0][cell] = f.x;
        s_tile[4 * v + 1][cell] = f.y;
        s_tile[4 * v + 2][cell] = f.z;
        s_tile[4 * v + 3][cell] = f.w;
    }
    __syncthreads();

    // Phase 3: coalesced float4 stores. Item j = (channel c, quad q of 4 x).
    // 64 channels * 27 quads = 1728 items.
    size_t outbase = (size_t)b * (C_ * NY_ * NX_) + (size_t)y * NX_ + x0;
    const int4* s_idx4 = (const int4*)s_idx;
    for (int j = tid; j < C_ * (TILE / 4); j += 256) {
        int c = j / (TILE / 4);
        int q = j - c * (TILE / 4);
        int4  m = s_idx4[q];
        // LDS.128 from padded row (PITCH%4==0 -> 16B aligned)
        const float4* row4 = (const float4*)s_tile[c];
        float4 t = row4[q];
        float4 v;
        v.x = (m.x < 0) ? 0.0f : t.x;
        v.y = (m.y < 0) ? 0.0f : t.y;
        v.z = (m.z < 0) ? 0.0f : t.z;
        v.w = (m.w < 0) ? 0.0f : t.w;
        *(float4*)(out + outbase + (size_t)c * (NY_ * NX_) + 4 * q) = v;
    }
}

// ---------------------------------------------------------------------------
extern "C" void kernel_launch(void* const* d_in, const int* in_sizes, int n_in,
                              void* d_out, int out_size) {
    const float* feat   = (const float*)d_in[0];
    const void*  coords = d_in[1];
    int P = in_sizes[0] / C_;   // features are [P, 64] f32

    constexpr int TPB = 256;
    detect_dtype_kernel<<<1, 32>>>(coords, P);
    fill_idxmap_kernel<<<(NCELLS / 4 + TPB - 1) / TPB, TPB>>>();
    scatter_idx_kernel<<<(P + TPB - 1) / TPB, TPB>>>(coords, P);
    gather_kernel<<<B_ * NY_ * TILES_X, TPB>>>(feat, (float*)d_out);
}

// round 6
// speedup vs baseline: 1.3780x; 1.0728x over previous
#include <cuda_runtime.h>
#include <cstdint>

// PointPillarScatter on GB300 (sm_103a).
// out[b, c, y, x] = feat[p, c] where idxmap[b, y, x] == p, else 0.
//
// Round 5 -> 6: fix the inverted empty-quad predicate. Round 5 used
// (m.x|m.y|m.z|m.w) >= 0, which is negative whenever ANY cell is -1 ->
// zeros written for every partially-occupied quad (rel_err ~1). Correct
// test is "any component >= 0". PITCH=116 conflict fix and merged
// fill+detect kernel retained.

#define NX_ 432
#define NY_ 496
#define C_  64
#define B_  8
#define NCELLS (B_ * NY_ * NX_)      // 1,714,176
#define TILE   108                   // x-cells per block (432/4)
#define TILES_X (NX_ / TILE)         // 4
#define PITCH  116                   // %4==0 (LDS.128); 4*PITCH%32=16 (bank split)

__device__ __align__(16) int g_idxmap[NCELLS];
__device__ int g_is64;   // 1 if coords buffer is int64, 0 if int32

// ---------------------------------------------------------------------------
// Kernel 1: fill idxmap with -1 (int4) + dtype detection (warp 0 of block 0).
// Genuine int64 coords read as int64 are all small non-negative ints; int32
// data read as int64 packs (y | x<<32) -> huge. 64 rows voted => robust.
// ---------------------------------------------------------------------------
__global__ void fill_and_detect_kernel(const void* __restrict__ coords, int P) {
    if (blockIdx.x == 0 && threadIdx.x < 32) {
        const long long* c64 = (const long long*)coords;
        int rows = P < 64 ? P : 64;
        int ok = 1;
        for (int p = threadIdx.x; p < rows; p += 32) {
            for (int j = 0; j < 4; j++) {
                long long v = c64[4 * p + j];
                if (v < 0 || v >= (1LL << 20)) ok = 0;
            }
        }
        ok = __all_sync(0xFFFFFFFFu, ok);
        if (threadIdx.x == 0) g_is64 = ok;
    }
    int i = blockIdx.x * blockDim.x + threadIdx.x;
    if (i < NCELLS / 4) {
        reinterpret_cast<int4*>(g_idxmap)[i] = make_int4(-1, -1, -1, -1);
    }
}

// ---------------------------------------------------------------------------
// Kernel 2: scatter pillar index, dtype-dispatched + bounds-guarded.
// coords row layout: (batch, z, y, x).
// ---------------------------------------------------------------------------
__global__ void scatter_idx_kernel(const void* __restrict__ coords, int P) {
    int p = blockIdx.x * blockDim.x + threadIdx.x;
    if (p >= P) return;
    int b, z, y, x;
    if (g_is64) {
        const long long* c = (const long long*)coords;
        b = (int)c[4 * p + 0]; z = (int)c[4 * p + 1];
        y = (int)c[4 * p + 2]; x = (int)c[4 * p + 3];
    } else {
        const int* c = (const int*)coords;
        b = c[4 * p + 0]; z = c[4 * p + 1];
        y = c[4 * p + 2]; x = c[4 * p + 3];
    }
    if (b < 0 || b >= B_) return;
    int lin = z + y * NX_ + x;
    if (lin < 0 || lin >= NY_ * NX_) return;
    g_idxmap[b * (NY_ * NX_) + lin] = p;
}

// ---------------------------------------------------------------------------
// Kernel 3: tiled gather/transpose. Block = one (b, y, 108 x-cells), 256 thr.
// ---------------------------------------------------------------------------
__global__ __launch_bounds__(256) void gather_kernel(const float* __restrict__ feat,
                                                     float* __restrict__ out) {
    __shared__ float s_tile[C_][PITCH];
    __shared__ __align__(16) int s_idx[PITCH];   // pillar index per cell (-1 empty)
    __shared__ int s_list[TILE];                 // compacted occupied cell ids
    __shared__ int s_n;

    int bx   = blockIdx.x;
    int tx   = bx % TILES_X;
    int y    = (bx / TILES_X) % NY_;
    int b    = bx / (TILES_X * NY_);
    int x0   = tx * TILE;
    int tid  = threadIdx.x;

    if (tid == 0) s_n = 0;
    if (tid >= TILE && tid < PITCH) s_idx[tid] = -1;   // pad cells invalid
    __syncthreads();

    // Phase 1: load idxmap once per cell; compact occupied cells.
    int cellbase = b * (NY_ * NX_) + y * NX_ + x0;
    if (tid < TILE) {
        int m = g_idxmap[cellbase + tid];
        s_idx[tid] = m;
        if (m >= 0) {
            int pos = atomicAdd(&s_n, 1);
            s_list[pos] = tid;
        }
    }
    __syncthreads();

    // Phase 2: contiguous vectorized feature reads for occupied cells only.
    // Item j = (occupied slot, float4 chunk v of the 256B feature row).
    int n_occ = s_n;
    const float4* feat4 = (const float4*)feat;
    for (int j = tid; j < n_occ * 16; j += 256) {
        int slot = j >> 4;
        int v    = j & 15;
        int cell = s_list[slot];
        int p    = s_idx[cell];
        float4 f = feat4[(size_t)p * 16 + v];
        s_tile[4 * v + 0][cell] = f.x;
        s_tile[4 * v + 1][cell] = f.y;
        s_tile[4 * v + 2][cell] = f.z;
        s_tile[4 * v + 3][cell] = f.w;
    }
    __syncthreads();

    // Phase 3: coalesced float4 stores; skip tile read for all-empty quads.
    // Item j = (channel c, quad q). 64 * 27 = 1728 items.
    size_t outbase = (size_t)b * (C_ * NY_ * NX_) + (size_t)y * NX_ + x0;
    const int4* s_idx4 = (const int4*)s_idx;
    for (int j = tid; j < C_ * (TILE / 4); j += 256) {
        int c = j / (TILE / 4);
        int q = j - c * (TILE / 4);
        int4  m = s_idx4[q];
        float4 v = make_float4(0.0f, 0.0f, 0.0f, 0.0f);
        // ANY cell occupied? (component-wise; a -1 must not veto the quad)
        if ((m.x >= 0) | (m.y >= 0) | (m.z >= 0) | (m.w >= 0)) {
            const float4* row4 = (const float4*)s_tile[c];
            float4 t = row4[q];               // LDS.128
            if (m.x >= 0) v.x = t.x;
            if (m.y >= 0) v.y = t.y;
            if (m.z >= 0) v.z = t.z;
            if (m.w >= 0) v.w = t.w;
        }
        *(float4*)(out + outbase + (size_t)c * (NY_ * NX_) + 4 * q) = v;
    }
}

// ---------------------------------------------------------------------------
extern "C" void kernel_launch(void* const* d_in, const int* in_sizes, int n_in,
                              void* d_out, int out_size) {
    const float* feat   = (const float*)d_in[0];
    const void*  coords = d_in[1];
    int P = in_sizes[0] / C_;   // features are [P, 64] f32

    constexpr int TPB = 256;
    fill_and_detect_kernel<<<(NCELLS / 4 + TPB - 1) / TPB, TPB>>>(coords, P);
    scatter_idx_kernel<<<(P + TPB - 1) / TPB, TPB>>>(coords, P);
    gather_kernel<<<B_ * NY_ * TILES_X, TPB>>>(feat, (float*)d_out);
}

// round 8
// speedup vs baseline: 1.4889x; 1.0805x over previous
#include <cuda_runtime.h>
#include <cstdint>

// PointPillarScatter on GB300 (sm_103a).
// out[b, c, y, x] = feat[p, c] where idxmap[b, y, x] == p, else 0.
//
// Round 7 -> 8: fix phase-3 coverage. R7 mapped (q, c0) from 256 threads but
// the space has 270 slots (27 quads x 10 channel-groups); slots 256..269
// (c0=9, q=13..26) were never written -> 4.9% of output left poisoned.
// Now: slot-strided loop covering all 270 slots. __stcs retained.

#define NX_ 432
#define NY_ 496
#define C_  64
#define B_  8
#define NCELLS (B_ * NY_ * NX_)      // 1,714,176
#define TILE   108                   // x-cells per block (432/4)
#define TILES_X (NX_ / TILE)         // 4
#define QUADS  (TILE / 4)            // 27
#define CGROUPS 10                   // ceil(64 / 10) channel-groups, stride 10
#define SLOTS  (QUADS * CGROUPS)     // 270
#define PITCH  116                   // %4==0 (LDS.128); 4*PITCH%32=16 (bank split)

__device__ __align__(16) int g_idxmap[NCELLS];
__device__ int g_is64;   // 1 if coords buffer is int64, 0 if int32

// ---------------------------------------------------------------------------
// Kernel 1: fill idxmap with -1 (int4) + dtype detection (warp 0 of block 0).
// ---------------------------------------------------------------------------
__global__ void fill_and_detect_kernel(const void* __restrict__ coords, int P) {
    if (blockIdx.x == 0 && threadIdx.x < 32) {
        const long long* c64 = (const long long*)coords;
        int rows = P < 64 ? P : 64;
        int ok = 1;
        for (int p = threadIdx.x; p < rows; p += 32) {
            for (int j = 0; j < 4; j++) {
                long long v = c64[4 * p + j];
                if (v < 0 || v >= (1LL << 20)) ok = 0;
            }
        }
        ok = __all_sync(0xFFFFFFFFu, ok);
        if (threadIdx.x == 0) g_is64 = ok;
    }
    int i = blockIdx.x * blockDim.x + threadIdx.x;
    if (i < NCELLS / 4) {
        reinterpret_cast<int4*>(g_idxmap)[i] = make_int4(-1, -1, -1, -1);
    }
}

// ---------------------------------------------------------------------------
// Kernel 2: scatter pillar index, dtype-dispatched + bounds-guarded.
// coords row layout: (batch, z, y, x).
// ---------------------------------------------------------------------------
__global__ void scatter_idx_kernel(const void* __restrict__ coords, int P) {
    int p = blockIdx.x * blockDim.x + threadIdx.x;
    if (p >= P) return;
    int b, z, y, x;
    if (g_is64) {
        const long long* c = (const long long*)coords;
        b = (int)c[4 * p + 0]; z = (int)c[4 * p + 1];
        y = (int)c[4 * p + 2]; x = (int)c[4 * p + 3];
    } else {
        const int* c = (const int*)coords;
        b = c[4 * p + 0]; z = c[4 * p + 1];
        y = c[4 * p + 2]; x = c[4 * p + 3];
    }
    if (b < 0 || b >= B_) return;
    int lin = z + y * NX_ + x;
    if (lin < 0 || lin >= NY_ * NX_) return;
    g_idxmap[b * (NY_ * NX_) + lin] = p;
}

// ---------------------------------------------------------------------------
// Kernel 3: tiled gather/transpose. Block = one (b, y, 108 x-cells), 256 thr.
// ---------------------------------------------------------------------------
__global__ __launch_bounds__(256) void gather_kernel(const float* __restrict__ feat,
                                                     float* __restrict__ out) {
    __shared__ float s_tile[C_][PITCH];
    __shared__ __align__(16) int s_idx[PITCH];   // pillar index per cell (-1 empty)
    __shared__ int s_list[TILE];                 // compacted occupied cell ids
    __shared__ int s_n;

    int bx   = blockIdx.x;
    int tx   = bx % TILES_X;
    int y    = (bx / TILES_X) % NY_;
    int b    = bx / (TILES_X * NY_);
    int x0   = tx * TILE;
    int tid  = threadIdx.x;

    if (tid == 0) s_n = 0;
    if (tid >= TILE && tid < PITCH) s_idx[tid] = -1;   // pad cells invalid
    __syncthreads();

    // Phase 1: load idxmap once per cell; compact occupied cells.
    int cellbase = b * (NY_ * NX_) + y * NX_ + x0;
    if (tid < TILE) {
        int m = g_idxmap[cellbase + tid];
        s_idx[tid] = m;
        if (m >= 0) {
            int pos = atomicAdd(&s_n, 1);
            s_list[pos] = tid;
        }
    }
    __syncthreads();

    // Phase 2: contiguous vectorized feature reads for occupied cells only.
    int n_occ = s_n;
    const float4* feat4 = (const float4*)feat;
    for (int j = tid; j < n_occ * 16; j += 256) {
        int slot = j >> 4;
        int v    = j & 15;
        int cell = s_list[slot];
        int p    = s_idx[cell];
        float4 f = feat4[(size_t)p * 16 + v];
        s_tile[4 * v + 0][cell] = f.x;
        s_tile[4 * v + 1][cell] = f.y;
        s_tile[4 * v + 2][cell] = f.z;
        s_tile[4 * v + 3][cell] = f.w;
    }
    __syncthreads();

    // Phase 3: coalesced streaming float4 stores. Slot space = 27 quads x
    // 10 channel-groups = 270; strided so all slots are covered by 256
    // threads. Per slot: hoisted validity mask, independent stride-10
    // channel chain (ILP on STG), tile read skipped for all-empty quads.
    size_t outbase = (size_t)b * (C_ * NY_ * NX_) + (size_t)y * NX_ + x0;
    const int4* s_idx4 = (const int4*)s_idx;
    for (int slot = tid; slot < SLOTS; slot += 256) {
        int q  = slot % QUADS;         // 0..26
        int c0 = slot / QUADS;         // 0..9
        int4  m = s_idx4[q];
        bool any = (m.x >= 0) | (m.y >= 0) | (m.z >= 0) | (m.w >= 0);
        float* outq = out + outbase + 4 * q;
        #pragma unroll
        for (int c = 0; c < C_; c += CGROUPS) {
            int cc = c + c0;
            if (cc >= C_) break;
            float4 v = make_float4(0.0f, 0.0f, 0.0f, 0.0f);
            if (any) {
                const float4* row4 = (const float4*)s_tile[cc];
                float4 t = row4[q];           // LDS.128
                if (m.x >= 0) v.x = t.x;
                if (m.y >= 0) v.y = t.y;
                if (m.z >= 0) v.z = t.z;
                if (m.w >= 0) v.w = t.w;
            }
            __stcs((float4*)(outq + (size_t)cc * (NY_ * NX_)), v);
        }
    }
}

// ---------------------------------------------------------------------------
extern "C" void kernel_launch(void* const* d_in, const int* in_sizes, int n_in,
                              void* d_out, int out_size) {
    const float* feat   = (const float*)d_in[0];
    const void*  coords = d_in[1];
    int P = in_sizes[0] / C_;   // features are [P, 64] f32

    constexpr int TPB = 256;
    fill_and_detect_kernel<<<(NCELLS / 4 + TPB - 1) / TPB, TPB>>>(coords, P);
    scatter_idx_kernel<<<(P + TPB - 1) / TPB, TPB>>>(coords, P);
    gather_kernel<<<B_ * NY_ * TILES_X, TPB>>>(feat, (float*)d_out);
}

// round 9
// speedup vs baseline: 1.5092x; 1.0136x over previous
#include <cuda_runtime.h>
#include <cstdint>

// PointPillarScatter on GB300 (sm_103a).
// out[b, c, y, x] = feat[p, c] where idxmap cell == p+1, else 0.
//
// Round 8 -> 9: remove the fill kernel (3 launches -> 2).
//  - idxmap encodes p+1 (0 = empty). __device__ globals are zero-init at
//    module load, so the first call needs no fill.
//  - The gather block that owns a tile zeroes every nonzero cell after
//    reading it -> idxmap is all-zero again at the end of every
//    kernel_launch, so graph replays are deterministic.
//  - dtype detection folded into the scatter kernel (per-block warp-0 scan
//    into smem; coords are L2-hot).

#define NX_ 432
#define NY_ 496
#define C_  64
#define B_  8
#define NCELLS (B_ * NY_ * NX_)      // 1,714,176
#define TILE   108                   // x-cells per block (432/4)
#define TILES_X (NX_ / TILE)         // 4
#define QUADS  (TILE / 4)            // 27
#define CGROUPS 10                   // channel-group stride
#define SLOTS  (QUADS * CGROUPS)     // 270
#define PITCH  116                   // %4==0 (LDS.128); 4*PITCH%32=16 (bank split)

__device__ __align__(16) int g_idxmap[NCELLS];   // zero-init = all empty

// ---------------------------------------------------------------------------
// Kernel 1: scatter pillar index (p+1), with per-block dtype detection.
// coords row layout: (batch, z, y, x). Bounds-guarded writes.
// ---------------------------------------------------------------------------
__global__ void scatter_idx_kernel(const void* __restrict__ coords, int P) {
    __shared__ int s_is64;
    if (threadIdx.x < 32) {
        // Genuine int64 coords read as int64 are small non-negative ints;
        // int32 data read as int64 packs two fields -> huge values.
        const long long* c64 = (const long long*)coords;
        int rows = P < 64 ? P : 64;
        int ok = 1;
        for (int p = threadIdx.x; p < rows; p += 32) {
            for (int j = 0; j < 4; j++) {
                long long v = c64[4 * p + j];
                if (v < 0 || v >= (1LL << 20)) ok = 0;
            }
        }
        ok = __all_sync(0xFFFFFFFFu, ok);
        if (threadIdx.x == 0) s_is64 = ok;
    }
    __syncthreads();

    int p = blockIdx.x * blockDim.x + threadIdx.x;
    if (p >= P) return;
    int b, z, y, x;
    if (s_is64) {
        const long long* c = (const long long*)coords;
        b = (int)c[4 * p + 0]; z = (int)c[4 * p + 1];
        y = (int)c[4 * p + 2]; x = (int)c[4 * p + 3];
    } else {
        const int* c = (const int*)coords;
        b = c[4 * p + 0]; z = c[4 * p + 1];
        y = c[4 * p + 2]; x = c[4 * p + 3];
    }
    if (b < 0 || b >= B_) return;
    int lin = z + y * NX_ + x;
    if (lin < 0 || lin >= NY_ * NX_) return;
    g_idxmap[b * (NY_ * NX_) + lin] = p + 1;     // 0 stays "empty"
}

// ---------------------------------------------------------------------------
// Kernel 2: tiled gather/transpose. Block = one (b, y, 108 x-cells), 256 thr.
// Self-cleans its idxmap slice for graph-replay determinism.
// ---------------------------------------------------------------------------
__global__ __launch_bounds__(256) void gather_kernel(const float* __restrict__ feat,
                                                     float* __restrict__ out) {
    __shared__ float s_tile[C_][PITCH];
    __shared__ __align__(16) int s_idx[PITCH];   // pillar index per cell (-1 empty)
    __shared__ int s_list[TILE];                 // compacted occupied cell ids
    __shared__ int s_n;

    int bx   = blockIdx.x;
    int tx   = bx % TILES_X;
    int y    = (bx / TILES_X) % NY_;
    int b    = bx / (TILES_X * NY_);
    int x0   = tx * TILE;
    int tid  = threadIdx.x;

    if (tid == 0) s_n = 0;
    if (tid >= TILE && tid < PITCH) s_idx[tid] = -1;   // pad cells invalid
    __syncthreads();

    // Phase 1: load idxmap once per cell; compact occupied; self-clean.
    int cellbase = b * (NY_ * NX_) + y * NX_ + x0;
    if (tid < TILE) {
        int m = g_idxmap[cellbase + tid];         // p+1, or 0 if empty
        if (m != 0) g_idxmap[cellbase + tid] = 0; // restore for next replay
        s_idx[tid] = m - 1;                       // p, or -1 if empty
        if (m > 0) {
            int pos = atomicAdd(&s_n, 1);
            s_list[pos] = tid;
        }
    }
    __syncthreads();

    // Phase 2: contiguous vectorized feature reads for occupied cells only.
    int n_occ = s_n;
    const float4* feat4 = (const float4*)feat;
    for (int j = tid; j < n_occ * 16; j += 256) {
        int slot = j >> 4;
        int v    = j & 15;
        int cell = s_list[slot];
        int p    = s_idx[cell];
        float4 f = feat4[(size_t)p * 16 + v];
        s_tile[4 * v + 0][cell] = f.x;
        s_tile[4 * v + 1][cell] = f.y;
        s_tile[4 * v + 2][cell] = f.z;
        s_tile[4 * v + 3][cell] = f.w;
    }
    __syncthreads();

    // Phase 3: coalesced streaming float4 stores over 270 (quad, c-group)
    // slots; hoisted validity mask, tile read skipped for all-empty quads.
    size_t outbase = (size_t)b * (C_ * NY_ * NX_) + (size_t)y * NX_ + x0;
    const int4* s_idx4 = (const int4*)s_idx;
    for (int slot = tid; slot < SLOTS; slot += 256) {
        int q  = slot % QUADS;         // 0..26
        int c0 = slot / QUADS;         // 0..9
        int4  m = s_idx4[q];
        bool any = (m.x >= 0) | (m.y >= 0) | (m.z >= 0) | (m.w >= 0);
        float* outq = out + outbase + 4 * q;
        #pragma unroll
        for (int c = 0; c < C_; c += CGROUPS) {
            int cc = c + c0;
            if (cc >= C_) break;
            float4 v = make_float4(0.0f, 0.0f, 0.0f, 0.0f);
            if (any) {
                const float4* row4 = (const float4*)s_tile[cc];
                float4 t = row4[q];           // LDS.128
                if (m.x >= 0) v.x = t.x;
                if (m.y >= 0) v.y = t.y;
                if (m.z >= 0) v.z = t.z;
                if (m.w >= 0) v.w = t.w;
            }
            __stcs((float4*)(outq + (size_t)cc * (NY_ * NX_)), v);
        }
    }
}

// ---------------------------------------------------------------------------
extern "C" void kernel_launch(void* const* d_in, const int* in_sizes, int n_in,
                              void* d_out, int out_size) {
    const float* feat   = (const float*)d_in[0];
    const void*  coords = d_in[1];
    int P = in_sizes[0] / C_;   // features are [P, 64] f32

    constexpr int TPB = 256;
    scatter_idx_kernel<<<(P + TPB - 1) / TPB, TPB>>>(coords, P);
    gather_kernel<<<B_ * NY_ * TILES_X, TPB>>>(feat, (float*)d_out);
}

// round 10
// speedup vs baseline: 1.5243x; 1.0100x over previous
#include <cuda_runtime.h>
#include <cstdint>

// PointPillarScatter on GB300 (sm_103a).
// out[b, c, y, x] = feat[p, c] where idxmap cell == p+1, else 0.
//
// Round 9 -> 10: gather was concurrency-bound (no pipe >60%, occ 72.6%,
// 7 blocks/SM on 31 KB smem). Channels processed in TWO halves of 32 ->
// smem 15.8 KB -> 8 blocks/SM (thread-capped) = full 64-warp occupancy.
// Phase-2 conflicts also drop 8-way -> 4-way (8 lanes share a pillar).

#define NX_ 432
#define NY_ 496
#define C_  64
#define CH_ 32                       // channels per half
#define B_  8
#define NCELLS (B_ * NY_ * NX_)      // 1,714,176
#define TILE   108                   // x-cells per block (432/4)
#define TILES_X (NX_ / TILE)         // 4
#define QUADS  (TILE / 4)            // 27
#define CGROUPS 10                   // channel-group stride (covers 0..31 from c0 0..9)
#define SLOTS  (QUADS * CGROUPS)     // 270
#define PITCH  116                   // %4==0 (LDS.128); 4*PITCH%32=16 (bank split)

__device__ __align__(16) int g_idxmap[NCELLS];   // zero-init = all empty

// ---------------------------------------------------------------------------
// Kernel 1: scatter pillar index (p+1), with per-block dtype detection.
// coords row layout: (batch, z, y, x). Bounds-guarded writes.
// ---------------------------------------------------------------------------
__global__ void scatter_idx_kernel(const void* __restrict__ coords, int P) {
    __shared__ int s_is64;
    if (threadIdx.x < 32) {
        const long long* c64 = (const long long*)coords;
        int rows = P < 64 ? P : 64;
        int ok = 1;
        for (int p = threadIdx.x; p < rows; p += 32) {
            for (int j = 0; j < 4; j++) {
                long long v = c64[4 * p + j];
                if (v < 0 || v >= (1LL << 20)) ok = 0;
            }
        }
        ok = __all_sync(0xFFFFFFFFu, ok);
        if (threadIdx.x == 0) s_is64 = ok;
    }
    __syncthreads();

    int p = blockIdx.x * blockDim.x + threadIdx.x;
    if (p >= P) return;
    int b, z, y, x;
    if (s_is64) {
        const long long* c = (const long long*)coords;
        b = (int)c[4 * p + 0]; z = (int)c[4 * p + 1];
        y = (int)c[4 * p + 2]; x = (int)c[4 * p + 3];
    } else {
        const int* c = (const int*)coords;
        b = c[4 * p + 0]; z = c[4 * p + 1];
        y = c[4 * p + 2]; x = c[4 * p + 3];
    }
    if (b < 0 || b >= B_) return;
    int lin = z + y * NX_ + x;
    if (lin < 0 || lin >= NY_ * NX_) return;
    g_idxmap[b * (NY_ * NX_) + lin] = p + 1;     // 0 stays "empty"
}

// ---------------------------------------------------------------------------
// Kernel 2: tiled gather/transpose, channel-halved for full occupancy.
// Block = one (b, y, 108 x-cells), 256 threads, smem ~15.8 KB.
// Self-cleans its idxmap slice for graph-replay determinism.
// ---------------------------------------------------------------------------
__global__ __launch_bounds__(256) void gather_kernel(const float* __restrict__ feat,
                                                     float* __restrict__ out) {
    __shared__ float s_tile[CH_][PITCH];
    __shared__ __align__(16) int s_idx[PITCH];   // pillar index per cell (-1 empty)
    __shared__ int s_list[TILE];                 // compacted occupied cell ids
    __shared__ int s_n;

    int bx   = blockIdx.x;
    int tx   = bx % TILES_X;
    int y    = (bx / TILES_X) % NY_;
    int b    = bx / (TILES_X * NY_);
    int x0   = tx * TILE;
    int tid  = threadIdx.x;

    if (tid == 0) s_n = 0;
    if (tid >= TILE && tid < PITCH) s_idx[tid] = -1;   // pad cells invalid
    __syncthreads();

    // Phase 1: load idxmap once per cell; compact occupied; self-clean.
    int cellbase = b * (NY_ * NX_) + y * NX_ + x0;
    if (tid < TILE) {
        int m = g_idxmap[cellbase + tid];         // p+1, or 0 if empty
        if (m != 0) g_idxmap[cellbase + tid] = 0; // restore for next replay
        s_idx[tid] = m - 1;                       // p, or -1 if empty
        if (m > 0) {
            int pos = atomicAdd(&s_n, 1);
            s_list[pos] = tid;
        }
    }
    __syncthreads();

    int n_occ = s_n;
    const float4* feat4 = (const float4*)feat;
    size_t outbase = (size_t)b * (C_ * NY_ * NX_) + (size_t)y * NX_ + x0;
    const int4* s_idx4 = (const int4*)s_idx;

    #pragma unroll
    for (int half = 0; half < 2; half++) {
        // Phase 2 (half): feature reads for channels [32*half, 32*half+32).
        // Item j = (occupied slot, float4 chunk v of this half's 128B).
        for (int j = tid; j < n_occ * 8; j += 256) {
            int slot = j >> 3;
            int v    = j & 7;
            int cell = s_list[slot];
            int p    = s_idx[cell];
            float4 f = feat4[(size_t)p * 16 + half * 8 + v];
            s_tile[4 * v + 0][cell] = f.x;
            s_tile[4 * v + 1][cell] = f.y;
            s_tile[4 * v + 2][cell] = f.z;
            s_tile[4 * v + 3][cell] = f.w;
        }
        __syncthreads();

        // Phase 3 (half): streaming float4 stores over 270 (quad, c-group)
        // slots; c in {c0, c0+10, c0+20, c0+30} ∩ [0,32) covers 0..31.
        const float* outh = out + outbase + (size_t)(half * CH_) * (NY_ * NX_);
        for (int slot = tid; slot < SLOTS; slot += 256) {
            int q  = slot % QUADS;         // 0..26
            int c0 = slot / QUADS;         // 0..9
            int4  m = s_idx4[q];
            bool any = (m.x >= 0) | (m.y >= 0) | (m.z >= 0) | (m.w >= 0);
            const float* outq = outh + 4 * q;
            #pragma unroll
            for (int c = 0; c < CH_; c += CGROUPS) {
                int cc = c + c0;
                if (cc >= CH_) break;
                float4 v = make_float4(0.0f, 0.0f, 0.0f, 0.0f);
                if (any) {
                    const float4* row4 = (const float4*)s_tile[cc];
                    float4 t = row4[q];           // LDS.128
                    if (m.x >= 0) v.x = t.x;
                    if (m.y >= 0) v.y = t.y;
                    if (m.z >= 0) v.z = t.z;
                    if (m.w >= 0) v.w = t.w;
                }
                __stcs((float4*)(outq + (size_t)cc * (NY_ * NX_)), v);
            }
        }
        if (half == 0) __syncthreads();   // tile reused by half 1
    }
}

// ---------------------------------------------------------------------------
extern "C" void kernel_launch(void* const* d_in, const int* in_sizes, int n_in,
                              void* d_out, int out_size) {
    const float* feat   = (const float*)d_in[0];
    const void*  coords = d_in[1];
    int P = in_sizes[0] / C_;   // features are [P, 64] f32

    constexpr int TPB = 256;
    scatter_idx_kernel<<<(P + TPB - 1) / TPB, TPB>>>(coords, P);
    gather_kernel<<<B_ * NY_ * TILES_X, TPB>>>(feat, (float*)d_out);
}